// round 12
// baseline (speedup 1.0000x reference)
#include <cuda_runtime.h>
#include <cuda_fp16.h>
#include <cstdint>

// Problem constants
#define BB    2
#define SS    2048
#define DM    1024
#define NH    16
#define NKV   4
#define DH    64
#define ROWS  (BB*SS)          // 4096
#define WINDOW 256
#define NGLOB  4
#define NQKV  1536             // fused QKV width

// ---------------------------------------------------------------------------
// Scratch (device globals; no allocation allowed)
// ---------------------------------------------------------------------------
__device__ __half g_qkvh [ROWS * NQKV];       // fused QKV, fp16 (GEMM epilogue; normrope in-place)
__device__ __half g_xh   [ROWS * DM];         // x fp16
__device__ __half g_ctxh [ROWS * DM];         // ctx fp16 (attention epilogue)
__device__ __half g_wqkvT[NQKV * DM];         // [Wq|Wk|Wv]^T fp16
__device__ __half g_woT  [DM * DM];           // Wo^T fp16

// ---------------------------------------------------------------------------
// Conversion kernels
// ---------------------------------------------------------------------------
__global__ void __launch_bounds__(256) conv_x_kernel(const float* __restrict__ in)
{
    int idx = blockIdx.x * blockDim.x + threadIdx.x;
    if (idx >= (ROWS * DM) / 4) return;
    float4 v = ((const float4*)in)[idx];
    ((__half2*)g_xh)[idx * 2]     = __floats2half2_rn(v.x, v.y);
    ((__half2*)g_xh)[idx * 2 + 1] = __floats2half2_rn(v.z, v.w);
}

// Tiled transpose+convert: W [1024, N] fp32 -> dst [N, 1024] fp16.
// z selects source. block (32,8), grid (32, 32, 4); small-N z slices guard.
__global__ void __launch_bounds__(256) conv_weights_kernel(
    const float* __restrict__ Wq, const float* __restrict__ Wk,
    const float* __restrict__ Wv, const float* __restrict__ Wo)
{
    __shared__ float t[32][33];
    const int z = blockIdx.z;
    const float* src; __half* dst; int N;
    if (z == 0)      { src = Wq; dst = g_wqkvT;                     N = 1024; }
    else if (z == 1) { src = Wk; dst = g_wqkvT + (size_t)1024 * DM; N = 256;  }
    else if (z == 2) { src = Wv; dst = g_wqkvT + (size_t)1280 * DM; N = 256;  }
    else             { src = Wo; dst = g_woT;                       N = 1024; }

    const int nb = blockIdx.x * 32, kb = blockIdx.y * 32;
    if (nb >= N) return;
    const int tx = threadIdx.x, ty = threadIdx.y;
    #pragma unroll
    for (int i = 0; i < 32; i += 8)
        t[ty + i][tx] = src[(size_t)(kb + ty + i) * N + nb + tx];
    __syncthreads();
    #pragma unroll
    for (int i = 0; i < 32; i += 8)
        dst[(size_t)(nb + ty + i) * DM + kb + tx] = __float2half(t[tx][ty + i]);
}

// ---------------------------------------------------------------------------
// HMMA helpers (fp16)
// ---------------------------------------------------------------------------
__device__ __forceinline__ uint32_t smem_u32(const void* p) {
    uint32_t a;
    asm("{ .reg .u64 t; cvta.to.shared.u64 t, %1; cvt.u32.u64 %0, t; }" : "=r"(a) : "l"(p));
    return a;
}
__device__ __forceinline__ void ldsm4(uint32_t* r, uint32_t addr) {
    asm volatile("ldmatrix.sync.aligned.m8n8.x4.shared.b16 {%0,%1,%2,%3}, [%4];"
                 : "=r"(r[0]), "=r"(r[1]), "=r"(r[2]), "=r"(r[3]) : "r"(addr));
}
__device__ __forceinline__ void ldsm4t(uint32_t* r, uint32_t addr) {
    asm volatile("ldmatrix.sync.aligned.m8n8.x4.trans.shared.b16 {%0,%1,%2,%3}, [%4];"
                 : "=r"(r[0]), "=r"(r[1]), "=r"(r[2]), "=r"(r[3]) : "r"(addr));
}
__device__ __forceinline__ void mma16816h(float* d, const uint32_t* a, uint32_t b0, uint32_t b1) {
    asm volatile("mma.sync.aligned.m16n8k16.row.col.f32.f16.f16.f32 "
                 "{%0,%1,%2,%3}, {%4,%5,%6,%7}, {%8,%9}, {%0,%1,%2,%3};"
                 : "+f"(d[0]), "+f"(d[1]), "+f"(d[2]), "+f"(d[3])
                 : "r"(a[0]), "r"(a[1]), "r"(a[2]), "r"(a[3]), "r"(b0), "r"(b1));
}
__device__ __forceinline__ void cp16(uint32_t dst, const void* src) {
    asm volatile("cp.async.cg.shared.global [%0], [%1], 16;" :: "r"(dst), "l"(src) : "memory");
}
__device__ __forceinline__ void cp_commit() {
    asm volatile("cp.async.commit_group;" ::: "memory");
}
template <int N>
__device__ __forceinline__ void cp_wait() {
    asm volatile("cp.async.wait_group %0;" :: "n"(N) : "memory");
}
__device__ __forceinline__ uint32_t pkh(float a, float b) {
    __half2 t = __floats2half2_rn(a, b);
    return *(uint32_t*)&t;
}

// ---------------------------------------------------------------------------
// HMMA fp16 GEMM: C = A[M,Kt] @ B[N,Kt]^T. CTA 128x256, 8 warps, BK=32, 3-stage.
// qkv_mode=1: write fp16 to g_qkvh [ROWS,1536]; else fp32 to C.
// ---------------------------------------------------------------------------
#define BK     32
#define ROWB   80
#define ATILE  (128 * ROWB)
#define BTILE  (256 * ROWB)
#define STAGE  (ATILE + BTILE)
#define GSMEM  (3 * STAGE)               // 92160

__global__ void __launch_bounds__(256) hmma_gemm2_kernel(
    const __half* __restrict__ A, const __half* __restrict__ B,
    float* __restrict__ C, int Kt, int ldc, int qkv_mode)
{
    extern __shared__ __align__(16) char dsm[];
    const int tid = threadIdx.x;
    const int wid = tid >> 5;
    const int lid = tid & 31;
    const int m0 = blockIdx.x * 128;
    const int n0 = blockIdx.y * 256;
    const int wm = (wid & 1) * 64;
    const int wn = (wid >> 1) * 64;

    uint32_t sA[3], sB[3];
    #pragma unroll
    for (int s = 0; s < 3; s++) {
        sA[s] = smem_u32(dsm + s * STAGE);
        sB[s] = sA[s] + ATILE;
    }

    float acc[4][8][4];
    #pragma unroll
    for (int i = 0; i < 4; i++)
        #pragma unroll
        for (int j = 0; j < 8; j++)
            #pragma unroll
            for (int q = 0; q < 4; q++) acc[i][j][q] = 0.f;

    const int ar = tid >> 2;
    const int ac = (tid & 3) * 16;
    const int NC = Kt / BK;

    #pragma unroll
    for (int c = 0; c < 2; c++) {
        const int k0e = c * BK + (ac >> 1);
        #pragma unroll
        for (int i = 0; i < 2; i++)
            cp16(sA[c] + (ar + i * 64) * ROWB + ac, A + (size_t)(m0 + ar + i * 64) * Kt + k0e);
        #pragma unroll
        for (int i = 0; i < 4; i++)
            cp16(sB[c] + (ar + i * 64) * ROWB + ac, B + (size_t)(n0 + ar + i * 64) * Kt + k0e);
        cp_commit();
    }

    int buf = 0, nbuf = 2;
    for (int c = 0; c < NC; c++) {
        cp_wait<1>();
        __syncthreads();

        if (c + 2 < NC) {
            const int k0e = (c + 2) * BK + (ac >> 1);
            #pragma unroll
            for (int i = 0; i < 2; i++)
                cp16(sA[nbuf] + (ar + i * 64) * ROWB + ac, A + (size_t)(m0 + ar + i * 64) * Kt + k0e);
            #pragma unroll
            for (int i = 0; i < 4; i++)
                cp16(sB[nbuf] + (ar + i * 64) * ROWB + ac, B + (size_t)(n0 + ar + i * 64) * Kt + k0e);
        }
        cp_commit();

        const int lr = lid & 15;
        const int lh = (lid >> 4) * 16;
        #pragma unroll
        for (int ks = 0; ks < 2; ks++) {
            const int kb = ks * 32;
            uint32_t am[4][4], bm[4][4];
            #pragma unroll
            for (int mf = 0; mf < 4; mf++)
                ldsm4(am[mf], sA[buf] + (wm + mf * 16 + lr) * ROWB + kb + lh);
            #pragma unroll
            for (int ng = 0; ng < 4; ng++)
                ldsm4(bm[ng], sB[buf] + (wn + ng * 16 + lr) * ROWB + kb + lh);
            #pragma unroll
            for (int mf = 0; mf < 4; mf++)
                #pragma unroll
                for (int nf = 0; nf < 8; nf++)
                    mma16816h(acc[mf][nf], am[mf], bm[nf >> 1][nf & 1], bm[nf >> 1][(nf & 1) + 2]);
        }
        buf = (buf == 2) ? 0 : buf + 1;
        nbuf = (nbuf == 2) ? 0 : nbuf + 1;
    }

    const int qr = lid >> 2;
    const int qc = (lid & 3) * 2;
    #pragma unroll
    for (int mf = 0; mf < 4; mf++) {
        const int row0 = m0 + wm + mf * 16 + qr;
        #pragma unroll
        for (int nf = 0; nf < 8; nf++) {
            const int col = n0 + wn + nf * 8 + qc;
            if (qkv_mode) {
                __half* v0 = g_qkvh + (size_t)row0 * NQKV + col;
                *(__half2*)v0              = __floats2half2_rn(acc[mf][nf][0], acc[mf][nf][1]);
                *(__half2*)(v0 + 8 * NQKV) = __floats2half2_rn(acc[mf][nf][2], acc[mf][nf][3]);
            } else {
                float* p0 = C + (size_t)row0 * ldc + col;
                float* p1 = p0 + 8 * ldc;
                p0[0] = acc[mf][nf][0]; p0[1] = acc[mf][nf][1];
                p1[0] = acc[mf][nf][2]; p1[1] = acc[mf][nf][3];
            }
        }
    }
}

// ---------------------------------------------------------------------------
// L2 normalize + RoPE, fp16 in-place in g_qkvh (Q cols 0..1023, K cols 1024..1279).
// ---------------------------------------------------------------------------
__global__ void __launch_bounds__(256) normrope_kernel(
    const float* __restrict__ cosp, const float* __restrict__ sinp)
{
    int w    = (blockIdx.x * blockDim.x + threadIdx.x) >> 5;
    int lane = threadIdx.x & 31;
    if (w >= ROWS * (NH + NKV)) return;
    int rg = w / (NH + NKV);
    int hh = w - rg * (NH + NKV);
    int s  = rg & (SS - 1);

    __half* base = g_qkvh + (size_t)rg * NQKV + (hh < NH ? hh * DH : 1024 + (hh - NH) * DH);

    float v0 = __half2float(base[lane]);
    float v1 = __half2float(base[lane + 32]);
    float ssq = v0*v0 + v1*v1;
    #pragma unroll
    for (int o = 16; o > 0; o >>= 1) ssq += __shfl_xor_sync(0xffffffffu, ssq, o);
    float inv = 1.0f / (sqrtf(ssq) + 1e-8f);

    float x1 = v0 * inv, x2 = v1 * inv;
    float c  = cosp[s*32 + lane];
    float sn = sinp[s*32 + lane];
    base[lane]      = __float2half(x1*c - x2*sn);
    base[lane + 32] = __float2half(x1*sn + x2*c);
}

// ---------------------------------------------------------------------------
// HMMA flash attention, K/V double-buffered (overlap tile load with compute).
// Q/K/V read from g_qkvh (stride 1536). Writes ctx fp16.
// ---------------------------------------------------------------------------
#define ASTR 144

__global__ void __launch_bounds__(128) attn_hmma_kernel()
{
    __shared__ __align__(16) char sQ[64*ASTR];
    __shared__ __align__(16) char sK[2][64*ASTR];
    __shared__ __align__(16) char sV[2][64*ASTR];

    const int qt = blockIdx.x, h = blockIdx.y, b = blockIdx.z;
    const int kh = h >> 2;
    const int tid = threadIdx.x;
    const int w = tid >> 5, l = tid & 31;
    const int qs = qt * 64;

    const uint32_t uQ = smem_u32(sQ);
    const uint32_t uK[2] = { smem_u32(sK[0]), smem_u32(sK[1]) };
    const uint32_t uV[2] = { smem_u32(sV[0]), smem_u32(sV[1]) };

    const int lrow = tid >> 3;             // 0..15 (+16i)
    const int lcol = (tid & 7) * 16;       // byte col

    // Q tile (group 0)
    {
        const char* qb = (const char*)(g_qkvh + (size_t)(b*SS + qs) * NQKV + h * DH);
        #pragma unroll
        for (int i = 0; i < 4; i++) {
            int r = lrow + i * 16;
            cp16(uQ + r * ASTR + lcol, qb + (size_t)r * (NQKV*2) + lcol);
        }
        cp_commit();
    }

    const int kt0 = (qs >= WINDOW) ? ((qs - (WINDOW-1)) >> 6) : 0;
    const int nsteps = qt - kt0 + 1 + (kt0 > 0 ? 1 : 0);

    auto kt_of = [&](int s) { return (kt0 > 0) ? (s == 0 ? 0 : kt0 + s - 1) : s; };
    auto load_kv = [&](int s, int bf) {
        const int kt = kt_of(s);
        const char* kb = (const char*)(g_qkvh + (size_t)(b*SS + kt*64) * NQKV + 1024 + kh * DH);
        const char* vb = kb + 256 * 2;   // V cols start 256 fp16 after K cols
        #pragma unroll
        for (int i = 0; i < 4; i++) {
            int r = lrow + i * 16;
            cp16(uK[bf] + r * ASTR + lcol, kb + (size_t)r * (NQKV*2) + lcol);
            cp16(uV[bf] + r * ASTR + lcol, vb + (size_t)r * (NQKV*2) + lcol);
        }
        cp_commit();
    };

    load_kv(0, 0);   // group 1

    float acc[8][4];
    #pragma unroll
    for (int j = 0; j < 8; j++)
        #pragma unroll
        for (int e = 0; e < 4; e++) acc[j][e] = 0.f;
    float lsum0 = 0.f, lsum1 = 0.f;

    for (int s = 0; s < nsteps; s++) {
        const int bf = s & 1;
        if (s + 1 < nsteps) {
            __syncthreads();            // all warps done reading buffer bf^1
            load_kv(s + 1, bf ^ 1);
            cp_wait<1>();               // step-s data (and Q) complete
        } else {
            cp_wait<0>();
        }
        __syncthreads();

        const int kt = kt_of(s);

        float sc[8][4];
        #pragma unroll
        for (int j = 0; j < 8; j++)
            #pragma unroll
            for (int e = 0; e < 4; e++) sc[j][e] = 0.f;

        #pragma unroll
        for (int kf = 0; kf < 4; kf++) {
            uint32_t am[4];
            ldsm4(am, uQ + ((w << 4) + (l & 15)) * ASTR + kf * 32 + ((l >> 4) << 4));
            #pragma unroll
            for (int ng = 0; ng < 4; ng++) {
                uint32_t bm[4];
                ldsm4(bm, uK[bf] + (16*ng + (l & 7) + ((l >> 4) << 3)) * ASTR
                              + kf * 32 + (((l >> 3) & 1) << 4));
                mma16816h(sc[2*ng],     am, bm[0], bm[1]);
                mma16816h(sc[2*ng + 1], am, bm[2], bm[3]);
            }
        }

        const int qa0 = qs + (w << 4) + (l >> 2);
        const int kbb = kt * 64 + 2 * (l & 3);
        #pragma unroll
        for (int j = 0; j < 8; j++) {
            const int kc = kbb + 8 * j;
            #pragma unroll
            for (int e = 0; e < 4; e++) {
                const int q_ = qa0 + ((e >> 1) << 3);
                const int k_ = kc + (e & 1);
                const bool v_ = (k_ <= q_) && ((k_ > q_ - WINDOW) || (k_ < NGLOB));
                float p = v_ ? __expf(0.125f * sc[j][e]) : 0.f;
                sc[j][e] = p;
                if (e < 2) lsum0 += p; else lsum1 += p;
            }
        }

        #pragma unroll
        for (int kf = 0; kf < 4; kf++) {
            uint32_t ah[4];
            ah[0] = pkh(sc[2*kf][0],     sc[2*kf][1]);
            ah[1] = pkh(sc[2*kf][2],     sc[2*kf][3]);
            ah[2] = pkh(sc[2*kf + 1][0], sc[2*kf + 1][1]);
            ah[3] = pkh(sc[2*kf + 1][2], sc[2*kf + 1][3]);

            const uint32_t voff = (16*kf + (l & 7) + (((l >> 3) & 1) << 3)) * ASTR
                                  + ((l >> 4) << 4);
            #pragma unroll
            for (int dg = 0; dg < 4; dg++) {
                uint32_t bh[4];
                ldsm4t(bh, uV[bf] + voff + dg * 32);
                mma16816h(acc[2*dg],     ah, bh[0], bh[1]);
                mma16816h(acc[2*dg + 1], ah, bh[2], bh[3]);
            }
        }
    }

    // epilogue: normalize + write ctx fp16
    lsum0 += __shfl_xor_sync(0xffffffffu, lsum0, 1, 4);
    lsum0 += __shfl_xor_sync(0xffffffffu, lsum0, 2, 4);
    lsum1 += __shfl_xor_sync(0xffffffffu, lsum1, 1, 4);
    lsum1 += __shfl_xor_sync(0xffffffffu, lsum1, 2, 4);
    const float i0 = 1.f / lsum0;
    const float i1 = 1.f / lsum1;

    const size_t row0 = (size_t)(b*SS + qs + (w << 4) + (l >> 2));
    __half* cb0 = g_ctxh + row0 * DM + h * DH + 2 * (l & 3);
    __half* cb1 = cb0 + 8 * DM;
    #pragma unroll
    for (int j = 0; j < 8; j++) {
        *(__half2*)(cb0 + 8*j) = __floats2half2_rn(acc[j][0] * i0, acc[j][1] * i0);
        *(__half2*)(cb1 + 8*j) = __floats2half2_rn(acc[j][2] * i1, acc[j][3] * i1);
    }
}

// ---------------------------------------------------------------------------
// Launch
// ---------------------------------------------------------------------------
extern "C" void kernel_launch(void* const* d_in, const int* in_sizes, int n_in,
                              void* d_out, int out_size)
{
    const float* x    = (const float*)d_in[0];
    const float* cosp = (const float*)d_in[1];
    const float* sinp = (const float*)d_in[2];
    // d_in[3] = mask: deterministic causal -> computed analytically in-kernel
    const float* Wq   = (const float*)d_in[4];
    const float* Wk   = (const float*)d_in[5];
    const float* Wv   = (const float*)d_in[6];
    const float* Wo   = (const float*)d_in[7];
    float* out = (float*)d_out;

    void *p_xh, *p_ch, *p_wqkvT, *p_woT;
    cudaGetSymbolAddress(&p_xh,    g_xh);
    cudaGetSymbolAddress(&p_ch,    g_ctxh);
    cudaGetSymbolAddress(&p_wqkvT, g_wqkvT);
    cudaGetSymbolAddress(&p_woT,   g_woT);

    cudaFuncSetAttribute(hmma_gemm2_kernel, cudaFuncAttributeMaxDynamicSharedMemorySize, GSMEM);

    // 0) Conversions
    conv_x_kernel<<<(ROWS*DM/4 + 255)/256, 256>>>(x);
    conv_weights_kernel<<<dim3(32, 32, 4), dim3(32, 8)>>>(Wq, Wk, Wv, Wo);

    // 1) Fused QKV projection (fp16 outputs straight into g_qkvh)
    hmma_gemm2_kernel<<<dim3(ROWS/128, NQKV/256), 256, GSMEM>>>(
        (const __half*)p_xh, (const __half*)p_wqkvT, nullptr, DM, NQKV, 1);

    // 2) L2 norm + RoPE in place (fp16)
    {
        int warps = ROWS * (NH + NKV);
        int blocks = (warps * 32 + 255) / 256;
        normrope_kernel<<<blocks, 256>>>(cosp, sinp);
    }

    // 3) Attention (fp16 HMMA, double-buffered K/V)
    attn_hmma_kernel<<<dim3(SS/64, NH, BB), 128>>>();

    // 4) Output projection
    hmma_gemm2_kernel<<<dim3(ROWS/128, DM/256), 256, GSMEM>>>(
        (const __half*)p_ch, (const __half*)p_woT, out, DM, DM, 0);
}

// round 13
// speedup vs baseline: 1.4543x; 1.4543x over previous
#include <cuda_runtime.h>
#include <cuda_fp16.h>
#include <cstdint>

// Problem constants
#define BB    2
#define SS    2048
#define DM    1024
#define NH    16
#define NKV   4
#define DH    64
#define ROWS  (BB*SS)          // 4096
#define WINDOW 256
#define NGLOB  4
#define NQKV  1536             // fused QKV output width

// ---------------------------------------------------------------------------
// Scratch (device globals; no allocation allowed)
// ---------------------------------------------------------------------------
__device__ float  g_qkvlin[ROWS * NQKV];      // fused QK projection (fp32; V cols unused)
__device__ __half g_xh    [ROWS * DM];        // x in fp16
__device__ __half g_ctxh  [ROWS * DM];        // ctx fp16 (attention epilogue)
__device__ __half g_wqkvT [NQKV * DM];        // [Wq|Wk|Wv]^T fp16
__device__ __half g_woT   [DM * DM];          // Wo^T fp16
// attention operands (fp16)
__device__ __half g_qbf[ROWS * (NH*DH)];
__device__ __half g_kbf[ROWS * (NKV*DH)];
__device__ __half g_vh [ROWS * (NKV*DH)];     // V single fp16 (written by GEMM epilogue)

// ---------------------------------------------------------------------------
// Conversion kernels
// ---------------------------------------------------------------------------
__global__ void __launch_bounds__(256) conv_x_kernel(const float* __restrict__ in)
{
    int idx = blockIdx.x * blockDim.x + threadIdx.x;
    if (idx >= (ROWS * DM) / 4) return;
    float4 v = ((const float4*)in)[idx];
    ((__half2*)g_xh)[idx * 2]     = __floats2half2_rn(v.x, v.y);
    ((__half2*)g_xh)[idx * 2 + 1] = __floats2half2_rn(v.z, v.w);
}

// Tiled transpose+convert: W [1024, N] fp32 -> dst [N, 1024] fp16.
// block (32,8), grid (32, 32, 4). Coalesced loads and stores.
__global__ void __launch_bounds__(256) conv_weights_kernel(
    const float* __restrict__ Wq, const float* __restrict__ Wk,
    const float* __restrict__ Wv, const float* __restrict__ Wo)
{
    __shared__ float t[32][33];
    const int z = blockIdx.z;
    const float* src; __half* dst; int N;
    if (z == 0)      { src = Wq; dst = g_wqkvT;                     N = 1024; }
    else if (z == 1) { src = Wk; dst = g_wqkvT + (size_t)1024 * DM; N = 256;  }
    else if (z == 2) { src = Wv; dst = g_wqkvT + (size_t)1280 * DM; N = 256;  }
    else             { src = Wo; dst = g_woT;                       N = 1024; }

    const int nb = blockIdx.x * 32, kb = blockIdx.y * 32;
    if (nb >= N) return;
    const int tx = threadIdx.x, ty = threadIdx.y;
    #pragma unroll
    for (int i = 0; i < 32; i += 8)
        t[ty + i][tx] = src[(size_t)(kb + ty + i) * N + nb + tx];
    __syncthreads();
    #pragma unroll
    for (int i = 0; i < 32; i += 8)
        dst[(size_t)(nb + ty + i) * DM + kb + tx] = __float2half(t[tx][ty + i]);
}

// ---------------------------------------------------------------------------
// HMMA helpers (fp16)
// ---------------------------------------------------------------------------
__device__ __forceinline__ uint32_t smem_u32(const void* p) {
    uint32_t a;
    asm("{ .reg .u64 t; cvta.to.shared.u64 t, %1; cvt.u32.u64 %0, t; }" : "=r"(a) : "l"(p));
    return a;
}
__device__ __forceinline__ void ldsm4(uint32_t* r, uint32_t addr) {
    asm volatile("ldmatrix.sync.aligned.m8n8.x4.shared.b16 {%0,%1,%2,%3}, [%4];"
                 : "=r"(r[0]), "=r"(r[1]), "=r"(r[2]), "=r"(r[3]) : "r"(addr));
}
__device__ __forceinline__ void ldsm4t(uint32_t* r, uint32_t addr) {
    asm volatile("ldmatrix.sync.aligned.m8n8.x4.trans.shared.b16 {%0,%1,%2,%3}, [%4];"
                 : "=r"(r[0]), "=r"(r[1]), "=r"(r[2]), "=r"(r[3]) : "r"(addr));
}
__device__ __forceinline__ void mma16816h(float* d, const uint32_t* a, uint32_t b0, uint32_t b1) {
    asm volatile("mma.sync.aligned.m16n8k16.row.col.f32.f16.f16.f32 "
                 "{%0,%1,%2,%3}, {%4,%5,%6,%7}, {%8,%9}, {%0,%1,%2,%3};"
                 : "+f"(d[0]), "+f"(d[1]), "+f"(d[2]), "+f"(d[3])
                 : "r"(a[0]), "r"(a[1]), "r"(a[2]), "r"(a[3]), "r"(b0), "r"(b1));
}
__device__ __forceinline__ void cp16(uint32_t dst, const void* src) {
    asm volatile("cp.async.cg.shared.global [%0], [%1], 16;" :: "r"(dst), "l"(src) : "memory");
}
__device__ __forceinline__ void cp_commit() {
    asm volatile("cp.async.commit_group;" ::: "memory");
}
template <int N>
__device__ __forceinline__ void cp_wait() {
    asm volatile("cp.async.wait_group %0;" :: "n"(N) : "memory");
}
__device__ __forceinline__ uint32_t pkh(float a, float b) {
    __half2 t = __floats2half2_rn(a, b);
    return *(uint32_t*)&t;
}

// ---------------------------------------------------------------------------
// HMMA fp16 GEMM: C[M,N] = A[M,Kt] @ B[N,Kt]^T
// CTA 128x256, 8 warps (2m x 4n of 64x64 warp tiles), BK=32, 3-stage cp.async.
// qkv_mode: N-cols >=1280 are V -> write single fp16 to g_vh instead of fp32 C.
// ---------------------------------------------------------------------------
#define BK     32
#define ROWB   80
#define ATILE  (128 * ROWB)
#define BTILE  (256 * ROWB)
#define STAGE  (ATILE + BTILE)
#define GSMEM  (3 * STAGE)               // 92160

__global__ void __launch_bounds__(256) hmma_gemm2_kernel(
    const __half* __restrict__ A, const __half* __restrict__ B,
    float* __restrict__ C, int Kt, int ldc, int qkv_mode)
{
    extern __shared__ __align__(16) char dsm[];
    const int tid = threadIdx.x;
    const int wid = tid >> 5;
    const int lid = tid & 31;
    const int m0 = blockIdx.x * 128;
    const int n0 = blockIdx.y * 256;
    const int wm = (wid & 1) * 64;
    const int wn = (wid >> 1) * 64;

    uint32_t sA[3], sB[3];
    #pragma unroll
    for (int s = 0; s < 3; s++) {
        sA[s] = smem_u32(dsm + s * STAGE);
        sB[s] = sA[s] + ATILE;
    }

    float acc[4][8][4];
    #pragma unroll
    for (int i = 0; i < 4; i++)
        #pragma unroll
        for (int j = 0; j < 8; j++)
            #pragma unroll
            for (int q = 0; q < 4; q++) acc[i][j][q] = 0.f;

    const int ar = tid >> 2;
    const int ac = (tid & 3) * 16;
    const int NC = Kt / BK;

    #pragma unroll
    for (int c = 0; c < 2; c++) {
        const int k0e = c * BK + (ac >> 1);
        #pragma unroll
        for (int i = 0; i < 2; i++)
            cp16(sA[c] + (ar + i * 64) * ROWB + ac, A + (size_t)(m0 + ar + i * 64) * Kt + k0e);
        #pragma unroll
        for (int i = 0; i < 4; i++)
            cp16(sB[c] + (ar + i * 64) * ROWB + ac, B + (size_t)(n0 + ar + i * 64) * Kt + k0e);
        cp_commit();
    }

    int buf = 0, nbuf = 2;
    for (int c = 0; c < NC; c++) {
        cp_wait<1>();
        __syncthreads();

        if (c + 2 < NC) {
            const int k0e = (c + 2) * BK + (ac >> 1);
            #pragma unroll
            for (int i = 0; i < 2; i++)
                cp16(sA[nbuf] + (ar + i * 64) * ROWB + ac, A + (size_t)(m0 + ar + i * 64) * Kt + k0e);
            #pragma unroll
            for (int i = 0; i < 4; i++)
                cp16(sB[nbuf] + (ar + i * 64) * ROWB + ac, B + (size_t)(n0 + ar + i * 64) * Kt + k0e);
        }
        cp_commit();

        const int lr = lid & 15;
        const int lh = (lid >> 4) * 16;
        #pragma unroll
        for (int ks = 0; ks < 2; ks++) {
            const int kb = ks * 32;
            uint32_t am[4][4], bm[4][4];
            #pragma unroll
            for (int mf = 0; mf < 4; mf++)
                ldsm4(am[mf], sA[buf] + (wm + mf * 16 + lr) * ROWB + kb + lh);
            #pragma unroll
            for (int ng = 0; ng < 4; ng++)
                ldsm4(bm[ng], sB[buf] + (wn + ng * 16 + lr) * ROWB + kb + lh);
            #pragma unroll
            for (int mf = 0; mf < 4; mf++)
                #pragma unroll
                for (int nf = 0; nf < 8; nf++)
                    mma16816h(acc[mf][nf], am[mf], bm[nf >> 1][nf & 1], bm[nf >> 1][(nf & 1) + 2]);
        }
        buf = (buf == 2) ? 0 : buf + 1;
        nbuf = (nbuf == 2) ? 0 : nbuf + 1;
    }

    const int qr = lid >> 2;
    const int qc = (lid & 3) * 2;
    #pragma unroll
    for (int mf = 0; mf < 4; mf++) {
        const int row0 = m0 + wm + mf * 16 + qr;
        #pragma unroll
        for (int nf = 0; nf < 8; nf++) {
            const int col = n0 + wn + nf * 8 + qc;
            if (qkv_mode && col >= 1280) {
                // V output: single fp16 into g_vh [ROWS, 256]
                __half* v0 = g_vh + (size_t)row0 * (NKV*DH) + (col - 1280);
                *(__half2*)v0                = __floats2half2_rn(acc[mf][nf][0], acc[mf][nf][1]);
                *(__half2*)(v0 + 8*(NKV*DH)) = __floats2half2_rn(acc[mf][nf][2], acc[mf][nf][3]);
            } else {
                float* p0 = C + (size_t)row0 * ldc + col;
                float* p1 = p0 + 8 * ldc;
                p0[0] = acc[mf][nf][0]; p0[1] = acc[mf][nf][1];
                p1[0] = acc[mf][nf][2]; p1[1] = acc[mf][nf][3];
            }
        }
    }
}

// ---------------------------------------------------------------------------
// L2 normalize + RoPE; reads fused fp32 proj, writes fp16 Q/K.
// ---------------------------------------------------------------------------
__global__ void __launch_bounds__(256) normrope_kernel(
    const float* __restrict__ cosp, const float* __restrict__ sinp)
{
    int w    = (blockIdx.x * blockDim.x + threadIdx.x) >> 5;
    int lane = threadIdx.x & 31;
    if (w >= ROWS * (NH + NKV)) return;
    int rg = w / (NH + NKV);
    int hh = w - rg * (NH + NKV);
    int s  = rg & (SS - 1);

    const float* base;
    __half* ob;
    if (hh < NH) {
        base = g_qkvlin + (size_t)rg * NQKV + hh * DH;
        ob   = g_qbf    + (size_t)rg * (NH*DH) + hh * DH;
    } else {
        base = g_qkvlin + (size_t)rg * NQKV + 1024 + (hh - NH) * DH;
        ob   = g_kbf    + (size_t)rg * (NKV*DH) + (hh - NH) * DH;
    }

    float v0 = base[lane];
    float v1 = base[lane + 32];
    float ssq = v0*v0 + v1*v1;
    #pragma unroll
    for (int o = 16; o > 0; o >>= 1) ssq += __shfl_xor_sync(0xffffffffu, ssq, o);
    float inv = 1.0f / (sqrtf(ssq) + 1e-8f);

    float x1 = v0 * inv, x2 = v1 * inv;
    float c  = cosp[s*32 + lane];
    float sn = sinp[s*32 + lane];
    ob[lane]      = __float2half(x1*c - x2*sn);
    ob[lane + 32] = __float2half(x1*sn + x2*c);
}

// ---------------------------------------------------------------------------
// HMMA flash attention (fp16): QK single, P single fp16, V single fp16 (1 PV product).
// Writes ctx as single fp16. Single-buffered K/V (proven 8-CTA/SM occupancy).
// ---------------------------------------------------------------------------
#define ASTR 144

__global__ void __launch_bounds__(128) attn_hmma_kernel()
{
    __shared__ __align__(16) char sQ[64*ASTR];
    __shared__ __align__(16) char sK[64*ASTR];
    __shared__ __align__(16) char sV[64*ASTR];

    const int qt = blockIdx.x, h = blockIdx.y, b = blockIdx.z;
    const int kh = h >> 2;
    const int tid = threadIdx.x;
    const int w = tid >> 5, l = tid & 31;
    const int qs = qt * 64;

    const uint32_t uQ = smem_u32(sQ), uK = smem_u32(sK), uV = smem_u32(sV);

    {
        const char* qb = (const char*)(g_qbf + (size_t)(b*SS + qs) * (NH*DH) + h * DH);
        #pragma unroll
        for (int i = 0; i < 4; i++) {
            int id = tid + i * 128;
            int r = id >> 3, c = (id & 7) * 16;
            cp16(uQ + r * ASTR + c, qb + (size_t)r * (NH*DH*2) + c);
        }
        cp_commit();
    }

    float acc[8][4];
    #pragma unroll
    for (int j = 0; j < 8; j++)
        #pragma unroll
        for (int e = 0; e < 4; e++) acc[j][e] = 0.f;
    float lsum0 = 0.f, lsum1 = 0.f;

    const int kt0 = (qs >= WINDOW) ? ((qs - (WINDOW-1)) >> 6) : 0;
    const int nsteps = qt - kt0 + 1 + (kt0 > 0 ? 1 : 0);

    for (int step = 0; step < nsteps; step++) {
        const int kt = (kt0 > 0) ? (step == 0 ? 0 : kt0 + step - 1) : step;

        __syncthreads();
        {
            const size_t roff = (size_t)(b*SS + kt*64) * (NKV*DH) + kh * DH;
            const char* kb = (const char*)(g_kbf + roff);
            const char* vb = (const char*)(g_vh  + roff);
            #pragma unroll
            for (int i = 0; i < 4; i++) {
                int id = tid + i * 128;
                int r = id >> 3, c = (id & 7) * 16;
                cp16(uK + r * ASTR + c, kb + (size_t)r * (NKV*DH*2) + c);
                cp16(uV + r * ASTR + c, vb + (size_t)r * (NKV*DH*2) + c);
            }
        }
        cp_commit();
        cp_wait<0>();
        __syncthreads();

        float sc[8][4];
        #pragma unroll
        for (int j = 0; j < 8; j++)
            #pragma unroll
            for (int e = 0; e < 4; e++) sc[j][e] = 0.f;

        #pragma unroll
        for (int kf = 0; kf < 4; kf++) {
            uint32_t am[4];
            ldsm4(am, uQ + ((w << 4) + (l & 15)) * ASTR + kf * 32 + ((l >> 4) << 4));
            #pragma unroll
            for (int ng = 0; ng < 4; ng++) {
                uint32_t bm[4];
                ldsm4(bm, uK + (16*ng + (l & 7) + ((l >> 4) << 3)) * ASTR
                             + kf * 32 + (((l >> 3) & 1) << 4));
                mma16816h(sc[2*ng],     am, bm[0], bm[1]);
                mma16816h(sc[2*ng + 1], am, bm[2], bm[3]);
            }
        }

        const int qa0 = qs + (w << 4) + (l >> 2);
        const int kbb = kt * 64 + 2 * (l & 3);
        #pragma unroll
        for (int j = 0; j < 8; j++) {
            const int kc = kbb + 8 * j;
            #pragma unroll
            for (int e = 0; e < 4; e++) {
                const int q_ = qa0 + ((e >> 1) << 3);
                const int k_ = kc + (e & 1);
                const bool v_ = (k_ <= q_) && ((k_ > q_ - WINDOW) || (k_ < NGLOB));
                float p = v_ ? __expf(0.125f * sc[j][e]) : 0.f;
                sc[j][e] = p;
                if (e < 2) lsum0 += p; else lsum1 += p;
            }
        }

        // PV: single product, P rounded to fp16 in registers
        #pragma unroll
        for (int kf = 0; kf < 4; kf++) {
            uint32_t ah[4];
            ah[0] = pkh(sc[2*kf][0],     sc[2*kf][1]);
            ah[1] = pkh(sc[2*kf][2],     sc[2*kf][3]);
            ah[2] = pkh(sc[2*kf + 1][0], sc[2*kf + 1][1]);
            ah[3] = pkh(sc[2*kf + 1][2], sc[2*kf + 1][3]);

            const uint32_t voff = (16*kf + (l & 7) + (((l >> 3) & 1) << 3)) * ASTR
                                  + ((l >> 4) << 4);
            #pragma unroll
            for (int dg = 0; dg < 4; dg++) {
                uint32_t bh[4];
                ldsm4t(bh, uV + voff + dg * 32);
                mma16816h(acc[2*dg],     ah, bh[0], bh[1]);
                mma16816h(acc[2*dg + 1], ah, bh[2], bh[3]);
            }
        }
    }

    // epilogue: normalize + write ctx single fp16
    lsum0 += __shfl_xor_sync(0xffffffffu, lsum0, 1, 4);
    lsum0 += __shfl_xor_sync(0xffffffffu, lsum0, 2, 4);
    lsum1 += __shfl_xor_sync(0xffffffffu, lsum1, 1, 4);
    lsum1 += __shfl_xor_sync(0xffffffffu, lsum1, 2, 4);
    const float i0 = 1.f / lsum0;
    const float i1 = 1.f / lsum1;

    const size_t row0 = (size_t)(b*SS + qs + (w << 4) + (l >> 2));
    __half* cb0 = g_ctxh + row0 * DM + h * DH + 2 * (l & 3);
    __half* cb1 = cb0 + 8 * DM;
    #pragma unroll
    for (int j = 0; j < 8; j++) {
        *(__half2*)(cb0 + 8*j) = __floats2half2_rn(acc[j][0] * i0, acc[j][1] * i0);
        *(__half2*)(cb1 + 8*j) = __floats2half2_rn(acc[j][2] * i1, acc[j][3] * i1);
    }
}

// ---------------------------------------------------------------------------
// Launch
// ---------------------------------------------------------------------------
extern "C" void kernel_launch(void* const* d_in, const int* in_sizes, int n_in,
                              void* d_out, int out_size)
{
    const float* x    = (const float*)d_in[0];
    const float* cosp = (const float*)d_in[1];
    const float* sinp = (const float*)d_in[2];
    // d_in[3] = mask: deterministic causal -> computed analytically in-kernel
    const float* Wq   = (const float*)d_in[4];
    const float* Wk   = (const float*)d_in[5];
    const float* Wv   = (const float*)d_in[6];
    const float* Wo   = (const float*)d_in[7];
    float* out = (float*)d_out;

    void *p_qkv, *p_xh, *p_ch, *p_wqkvT, *p_woT;
    cudaGetSymbolAddress(&p_qkv,   g_qkvlin);
    cudaGetSymbolAddress(&p_xh,    g_xh);
    cudaGetSymbolAddress(&p_ch,    g_ctxh);
    cudaGetSymbolAddress(&p_wqkvT, g_wqkvT);
    cudaGetSymbolAddress(&p_woT,   g_woT);

    cudaFuncSetAttribute(hmma_gemm2_kernel, cudaFuncAttributeMaxDynamicSharedMemorySize, GSMEM);

    // 0) Conversions (vectorized x; tiled transpose for weights)
    conv_x_kernel<<<(ROWS*DM/4 + 255)/256, 256>>>(x);
    conv_weights_kernel<<<dim3(32, 32, 4), dim3(32, 8)>>>(Wq, Wk, Wv, Wo);

    // 1) Fused QKV projection (V cols emitted as fp16 directly)
    hmma_gemm2_kernel<<<dim3(ROWS/128, NQKV/256), 256, GSMEM>>>(
        (const __half*)p_xh, (const __half*)p_wqkvT, (float*)p_qkv, DM, NQKV, 1);

    // 2) L2 norm + RoPE -> fp16 Q/K
    {
        int warps = ROWS * (NH + NKV);
        int blocks = (warps * 32 + 255) / 256;
        normrope_kernel<<<blocks, 256>>>(cosp, sinp);
    }

    // 3) Attention (fp16 HMMA, 1 PV product, writes fp16 ctx)
    attn_hmma_kernel<<<dim3(SS/64, NH, BB), 128>>>();

    // 4) Output projection (K=1024)
    hmma_gemm2_kernel<<<dim3(ROWS/128, DM/256), 256, GSMEM>>>(
        (const __half*)p_ch, (const __half*)p_woT, out, DM, DM, 0);
}